// round 11
// baseline (speedup 1.0000x reference)
#include <cuda_runtime.h>
#include <math.h>

#define BB  2048
#define SS  512
#define EE  384
#define FF  28
#define HH  32
#define SP1 513          // S+1 positions (trainable prefix + S)
#define SPAD 516         // scores padded so later members stay 16B-aligned
#define NW  16           // warps per block
#define NT  512          // threads per block
#define ND  4            // per-warp pipeline depth (slots)
#define GRID 256         // persistent; 2048/256 = exactly 8 batches per CTA

struct __align__(16) Smem {
    float stage[NW][ND][EE];   // 98304 B warp-private cp.async ring; slot0 reused as acc
    float qk[EE];              // 1536 B
    float norm[EE];            // 1536 B
    float ctx[EE];             // 1536 B
    float scores[SPAD];        // 2064 B (513 used)
    float q[HH];               // 128 B (float4-read, 16B-aligned)
    float doc[NW][HH];         // 2048 B
    float wd[NW];
    int   wcnt[NW];
    int   woff[NW + 1];
    float dotqbk, gd;
    short act[SS];
};

__device__ __forceinline__ float warp_sum(float v) {
    #pragma unroll
    for (int o = 16; o; o >>= 1) v += __shfl_xor_sync(0xffffffffu, v, o);
    return v;
}

__device__ __forceinline__ void cp16(void* dst_smem, const void* src) {
    unsigned d = (unsigned)__cvta_generic_to_shared(dst_smem);
    asm volatile("cp.async.cg.shared.global [%0], [%1], 16;\n" :: "r"(d), "l"(src));
}
#define CP_COMMIT() asm volatile("cp.async.commit_group;\n" ::: "memory")
#define CP_WAIT(n)  asm volatile("cp.async.wait_group %0;\n" :: "n"(n) : "memory")

__global__ __launch_bounds__(NT, 2)
void sent_attn_kernel(const float* __restrict__ emb,        // [B,S,E]
                      const int*   __restrict__ masks,      // [B,S]
                      const float* __restrict__ features,   // [B,F]
                      const float* __restrict__ W_map,      // [F,H]
                      const float* __restrict__ b_map,      // [H]
                      const float* __restrict__ trainable,  // [1,E]
                      const float* __restrict__ W_k,        // [E,H]
                      const float* __restrict__ b_k,        // [H]
                      const float* __restrict__ W_v,        // [E,H]
                      const float* __restrict__ b_v,        // [H]
                      const float* __restrict__ W_c,        // [2H,1]
                      const float* __restrict__ b_c,        // [1]
                      float*       __restrict__ out)        // [B] logits ++ [B,SP1] attn
{
    extern __shared__ __align__(16) char smem_raw[];
    Smem* sm = (Smem*)smem_raw;

    const int tid  = threadIdx.x;
    const int w    = tid >> 5;
    const int lane = tid & 31;

    for (int b = blockIdx.x; b < BB; b += GRID) {

    // ---------------- step 1: masks, q, normed trainable ------------------------
    const int active = (__ldcs(masks + (size_t)b * SS + tid) == 0);
    const unsigned bal = __ballot_sync(0xffffffffu, active);
    if (lane == 0) sm->wcnt[w] = __popc(bal);
    sm->scores[tid] = -INFINITY;
    if (tid == 0) sm->scores[SS] = -INFINITY;

    if (w == 0) {
        float acc = b_map[lane];
        const float* fb = features + b * FF;
        #pragma unroll
        for (int f = 0; f < FF; ++f)
            acc = fmaf(fb[f], W_map[f * HH + lane], acc);
        sm->q[lane] = acc;
    } else if (w == 1) {
        float ss = 0.f;
        #pragma unroll
        for (int j = 0; j < EE / 32; ++j) {
            float t = trainable[lane + 32 * j];
            ss = fmaf(t, t, ss);
        }
        ss = warp_sum(ss);
        float inv = rsqrtf(ss);
        #pragma unroll
        for (int j = 0; j < EE / 32; ++j)
            sm->norm[lane + 32 * j] = trainable[lane + 32 * j] * inv;
    }
    __syncthreads();

    // ---------------- step 2: scan of warp counts ; dot(q, b_k) -----------------
    if (w == 0) {
        int c = (lane < NW) ? sm->wcnt[lane] : 0;
        int sc = c;
        #pragma unroll
        for (int o = 1; o < NW; o <<= 1) {
            int t = __shfl_up_sync(0xffffffffu, sc, o);
            if (lane >= o) sc += t;
        }
        if (lane < NW) sm->woff[lane + 1] = sc;
        if (lane == 0) sm->woff[0] = 0;
    } else if (w == 1) {
        float p = sm->q[lane] * b_k[lane];        // HH == 32
        p = warp_sum(p);
        if (lane == 0) sm->dotqbk = p;
    }
    __syncthreads();

    // ---------------- step 3: compacted active-row list -------------------------
    if (active) {
        int pos = sm->woff[w] + __popc(bal & ((1u << lane) - 1u));
        sm->act[pos] = (short)tid;
    }
    __syncthreads();

    const int n_act = sm->woff[NW];
    const int nloc  = (w < n_act) ? ((n_act - 1 - w) / NW + 1) : 0;
    const float4* erow_base = (const float4*)emb + (size_t)b * SS * (EE / 4);

    // per-warp issue of local row i into its private slot i%ND (always commits)
    auto issue_row = [&](int i) {
        int idx = w + i * NW;
        if (idx < n_act) {
            int s = sm->act[idx];
            const float4* src = erow_base + (size_t)s * (EE / 4);
            float4* dst = (float4*)sm->stage[w][i & (ND - 1)];
            cp16(dst + lane,      src + lane);
            cp16(dst + lane + 32, src + lane + 32);
            cp16(dst + lane + 64, src + lane + 64);
        }
        CP_COMMIT();
    };

    // prime the per-warp pipeline BEFORE the qk prologue (DRAM busy during it)
    issue_row(0); issue_row(1); issue_row(2); issue_row(3);

    // ---------------- step 4: qk = W_k @ q, thread-per-e ------------------------
    if (tid < EE) {
        const float4* wk = (const float4*)(W_k + tid * HH);
        const float4* q4 = (const float4*)sm->q;
        float p = 0.f;
        #pragma unroll
        for (int j = 0; j < HH / 4; ++j) {
            float4 a = wk[j], qq = q4[j];
            p += a.x*qq.x + a.y*qq.y + a.z*qq.z + a.w*qq.w;
        }
        sm->qk[tid] = p;
    }
    __syncthreads();

    // ---------------- step 5: barrier-free per-warp streaming pass ---------------
    const float dq    = sm->dotqbk;
    const float scale = 0.17677669529663687f;        // 1/sqrt(32)
    const float4* qk4 = (const float4*)sm->qk;
    float4 k0 = qk4[lane], k1 = qk4[lane + 32], k2 = qk4[lane + 64];

    float  dsum = 0.f;
    float4 a0 = {0.f,0.f,0.f,0.f}, a1 = {0.f,0.f,0.f,0.f}, a2 = {0.f,0.f,0.f,0.f};

    // warp 0 seeds with the (never-masked) trainable prefix position
    if (w == 0) {
        const float4* n4 = (const float4*)sm->norm;
        float4 v0 = n4[lane], v1 = n4[lane + 32], v2 = n4[lane + 64];
        float p = v0.x*k0.x + v0.y*k0.y + v0.z*k0.z + v0.w*k0.w;
        p      += v1.x*k1.x + v1.y*k1.y + v1.z*k1.z + v1.w*k1.w;
        p      += v2.x*k2.x + v2.y*k2.y + v2.z*k2.z + v2.w*k2.w;
        p = warp_sum(p);
        float sc = (p + dq) * scale;
        float wt = __expf(sc);
        if (lane == 0) sm->scores[0] = sc;
        dsum = wt;
        a0.x = wt*v0.x; a0.y = wt*v0.y; a0.z = wt*v0.z; a0.w = wt*v0.w;
        a1.x = wt*v1.x; a1.y = wt*v1.y; a1.z = wt*v1.z; a1.w = wt*v1.w;
        a2.x = wt*v2.x; a2.y = wt*v2.y; a2.z = wt*v2.z; a2.w = wt*v2.w;
    }

    for (int i = 0; i < nloc; ++i) {
        CP_WAIT(ND - 1);                    // oldest group (local row i) complete
        const int s = sm->act[w + i * NW];
        const float4* r = (const float4*)sm->stage[w][i & (ND - 1)];
        float4 v0 = r[lane], v1 = r[lane + 32], v2 = r[lane + 64];

        float p = v0.x*k0.x + v0.y*k0.y + v0.z*k0.z + v0.w*k0.w;
        p      += v1.x*k1.x + v1.y*k1.y + v1.z*k1.z + v1.w*k1.w;
        p      += v2.x*k2.x + v2.y*k2.y + v2.z*k2.z + v2.w*k2.w;
        p = warp_sum(p);

        issue_row(i + ND);                  // refill the slot just consumed

        float sc = (p + dq) * scale;
        float wt = __expf(sc);
        if (lane == 0) sm->scores[s + 1] = sc;
        dsum += wt;
        a0.x = fmaf(wt, v0.x, a0.x); a0.y = fmaf(wt, v0.y, a0.y);
        a0.z = fmaf(wt, v0.z, a0.z); a0.w = fmaf(wt, v0.w, a0.w);
        a1.x = fmaf(wt, v1.x, a1.x); a1.y = fmaf(wt, v1.y, a1.y);
        a1.z = fmaf(wt, v1.z, a1.z); a1.w = fmaf(wt, v1.w, a1.w);
        a2.x = fmaf(wt, v2.x, a2.x); a2.y = fmaf(wt, v2.y, a2.y);
        a2.z = fmaf(wt, v2.z, a2.z); a2.w = fmaf(wt, v2.w, a2.w);
    }
    CP_WAIT(0);                             // drain (tail groups are empty commits)

    if (lane == 0) sm->wd[w] = dsum;
    {
        // reuse this warp's own stage slot 0 as its accumulator dump
        float4* arow = (float4*)sm->stage[w][0];
        arow[lane] = a0; arow[lane + 32] = a1; arow[lane + 64] = a2;
    }
    __syncthreads();

    // ---------------- merge: total denominator ----------------------------------
    if (w == 0) {
        float dd = (lane < NW) ? sm->wd[lane] : 0.f;
        dd = warp_sum(dd);
        if (lane == 0) sm->gd = dd;
    }
    __syncthreads();

    const float ginv = 1.f / sm->gd;

    // ctx[e] = (sum_w acc[w][e]) / D
    if (tid < EE) {
        float c = 0.f;
        #pragma unroll
        for (int ww = 0; ww < NW; ++ww)
            c += sm->stage[ww][0][tid];
        sm->ctx[tid] = c * ginv;
    }

    // attn_weight output (masked rows: exp(-inf)=0 exactly)
    {
        float* out_attn = out + BB + (size_t)b * SP1;
        for (int s = tid; s < SP1; s += NT)
            out_attn[s] = __expf(sm->scores[s]) * ginv;
    }
    __syncthreads();

    // ---------------- doc_repr = ctx @ W_v + b_v ; logits ------------------------
    {
        const int e0 = w * (EE / NW);                // 24-wide slabs
        float p = 0.f;
        #pragma unroll
        for (int j = 0; j < EE / NW; ++j)
            p = fmaf(sm->ctx[e0 + j], W_v[(e0 + j) * HH + lane], p);
        sm->doc[w][lane] = p;
    }
    __syncthreads();
    if (w == 0) {
        float dv = b_v[lane];
        #pragma unroll
        for (int g = 0; g < NW; ++g) dv += sm->doc[g][lane];
        float lg = fmaf(dv, W_c[lane], sm->q[lane] * W_c[HH + lane]);
        lg = warp_sum(lg);
        if (lane == 0) out[b] = lg + b_c[0];
    }
    __syncthreads();    // protect smem before next batch reuses it

    } // persistent batch loop
}

extern "C" void kernel_launch(void* const* d_in, const int* in_sizes, int n_in,
                              void* d_out, int out_size) {
    (void)in_sizes; (void)n_in; (void)out_size;
    const int smem_bytes = (int)sizeof(Smem);
    cudaFuncSetAttribute(sent_attn_kernel,
                         cudaFuncAttributeMaxDynamicSharedMemorySize, smem_bytes);
    sent_attn_kernel<<<GRID, NT, smem_bytes>>>(
        (const float*)d_in[0],   // embeddings
        (const int*  )d_in[1],   // masks
        (const float*)d_in[2],   // features
        (const float*)d_in[3],   // W_map
        (const float*)d_in[4],   // b_map
        (const float*)d_in[5],   // trainable
        (const float*)d_in[6],   // W_k
        (const float*)d_in[7],   // b_k
        (const float*)d_in[8],   // W_v
        (const float*)d_in[9],   // b_v
        (const float*)d_in[10],  // W_c
        (const float*)d_in[11],  // b_c
        (float*)d_out);
}

// round 12
// speedup vs baseline: 1.0652x; 1.0652x over previous
#include <cuda_runtime.h>
#include <math.h>

#define BB  2048
#define SS  512
#define EE  384
#define FF  28
#define HH  32
#define SP1 513          // S+1 positions (trainable prefix + S)
#define SPAD 516         // scores padded so later members stay 16B-aligned
#define NW  16           // warps per block
#define NT  512          // threads per block
#define ND  4            // per-warp pipeline depth (slots)
#define GRID 304         // persistent: 2 CTAs per SM

struct __align__(16) Smem {
    float stage[NW][ND][EE];   // 98304 B warp-private cp.async ring; slot0 reused as acc
    float qk[EE];              // 1536 B
    float norm[EE];            // 1536 B
    float ctx[EE];             // 1536 B
    float scores[SPAD];        // 2064 B (513 used)
    float q[HH];               // 128 B (float4-read, 16B-aligned)
    float doc[NW][HH];         // 2048 B
    float wd[NW];
    int   wcnt[NW];
    int   woff[NW + 1];
    float dotqbk;
    short act[SS];
};

__device__ __forceinline__ float warp_sum(float v) {
    #pragma unroll
    for (int o = 16; o; o >>= 1) v += __shfl_xor_sync(0xffffffffu, v, o);
    return v;
}

__device__ __forceinline__ void cp16(void* dst_smem, const void* src) {
    unsigned d = (unsigned)__cvta_generic_to_shared(dst_smem);
    asm volatile("cp.async.cg.shared.global [%0], [%1], 16;\n" :: "r"(d), "l"(src));
}
#define CP_COMMIT() asm volatile("cp.async.commit_group;\n" ::: "memory")
#define CP_WAIT(n)  asm volatile("cp.async.wait_group %0;\n" :: "n"(n) : "memory")

__global__ __launch_bounds__(NT, 2)
void sent_attn_kernel(const float* __restrict__ emb,        // [B,S,E]
                      const int*   __restrict__ masks,      // [B,S]
                      const float* __restrict__ features,   // [B,F]
                      const float* __restrict__ W_map,      // [F,H]
                      const float* __restrict__ b_map,      // [H]
                      const float* __restrict__ trainable,  // [1,E]
                      const float* __restrict__ W_k,        // [E,H]
                      const float* __restrict__ b_k,        // [H]
                      const float* __restrict__ W_v,        // [E,H]
                      const float* __restrict__ b_v,        // [H]
                      const float* __restrict__ W_c,        // [2H,1]
                      const float* __restrict__ b_c,        // [1]
                      float*       __restrict__ out)        // [B] logits ++ [B,SP1] attn
{
    extern __shared__ __align__(16) char smem_raw[];
    Smem* sm = (Smem*)smem_raw;

    const int tid  = threadIdx.x;
    const int w    = tid >> 5;
    const int lane = tid & 31;

    for (int b = blockIdx.x; b < BB; b += GRID) {

    // ---------------- step 1: masks, q, normed trainable ------------------------
    const int active = (__ldcs(masks + (size_t)b * SS + tid) == 0);
    const unsigned bal = __ballot_sync(0xffffffffu, active);
    if (lane == 0) sm->wcnt[w] = __popc(bal);
    sm->scores[tid] = -INFINITY;
    if (tid == 0) sm->scores[SS] = -INFINITY;

    if (w == 0) {
        float acc = b_map[lane];
        const float* fb = features + b * FF;
        #pragma unroll
        for (int f = 0; f < FF; ++f)
            acc = fmaf(fb[f], W_map[f * HH + lane], acc);
        sm->q[lane] = acc;
    } else if (w == 1) {
        float ss = 0.f;
        #pragma unroll
        for (int j = 0; j < EE / 32; ++j) {
            float t = trainable[lane + 32 * j];
            ss = fmaf(t, t, ss);
        }
        ss = warp_sum(ss);
        float inv = rsqrtf(ss);
        #pragma unroll
        for (int j = 0; j < EE / 32; ++j)
            sm->norm[lane + 32 * j] = trainable[lane + 32 * j] * inv;
    }
    __syncthreads();

    // ---------------- step 2: scan of warp counts ; dot(q, b_k) -----------------
    if (w == 0) {
        int c = (lane < NW) ? sm->wcnt[lane] : 0;
        int sc = c;
        #pragma unroll
        for (int o = 1; o < NW; o <<= 1) {
            int t = __shfl_up_sync(0xffffffffu, sc, o);
            if (lane >= o) sc += t;
        }
        if (lane < NW) sm->woff[lane + 1] = sc;
        if (lane == 0) sm->woff[0] = 0;
    } else if (w == 1) {
        float p = sm->q[lane] * b_k[lane];        // HH == 32
        p = warp_sum(p);
        if (lane == 0) sm->dotqbk = p;
    }
    __syncthreads();

    // ---------------- step 3: compacted active-row list -------------------------
    if (active) {
        int pos = sm->woff[w] + __popc(bal & ((1u << lane) - 1u));
        sm->act[pos] = (short)tid;
    }
    __syncthreads();

    const int n_act = sm->woff[NW];
    const int nloc  = (w < n_act) ? ((n_act - 1 - w) / NW + 1) : 0;
    const float4* erow_base = (const float4*)emb + (size_t)b * SS * (EE / 4);

    // per-warp issue of local row i into its private slot i%ND (always commits)
    auto issue_row = [&](int i) {
        int idx = w + i * NW;
        if (idx < n_act) {
            int s = sm->act[idx];
            const float4* src = erow_base + (size_t)s * (EE / 4);
            float4* dst = (float4*)sm->stage[w][i & (ND - 1)];
            cp16(dst + lane,      src + lane);
            cp16(dst + lane + 32, src + lane + 32);
            cp16(dst + lane + 64, src + lane + 64);
        }
        CP_COMMIT();
    };

    // prime the per-warp pipeline BEFORE the qk prologue (DRAM busy during it)
    issue_row(0); issue_row(1); issue_row(2); issue_row(3);

    // ---------------- step 4: qk = W_k @ q, thread-per-e ------------------------
    if (tid < EE) {
        const float4* wk = (const float4*)(W_k + tid * HH);
        const float4* q4 = (const float4*)sm->q;
        float p = 0.f;
        #pragma unroll
        for (int j = 0; j < HH / 4; ++j) {
            float4 a = wk[j], qq = q4[j];
            p += a.x*qq.x + a.y*qq.y + a.z*qq.z + a.w*qq.w;
        }
        sm->qk[tid] = p;
    }
    __syncthreads();

    // ---------------- step 5: barrier-free per-warp streaming pass ---------------
    const float dq    = sm->dotqbk;
    const float scale = 0.17677669529663687f;        // 1/sqrt(32)
    const float4* qk4 = (const float4*)sm->qk;
    float4 k0 = qk4[lane], k1 = qk4[lane + 32], k2 = qk4[lane + 64];

    float  dsum = 0.f;
    float4 a0 = {0.f,0.f,0.f,0.f}, a1 = {0.f,0.f,0.f,0.f}, a2 = {0.f,0.f,0.f,0.f};

    // warp 0 seeds with the (never-masked) trainable prefix position
    if (w == 0) {
        const float4* n4 = (const float4*)sm->norm;
        float4 v0 = n4[lane], v1 = n4[lane + 32], v2 = n4[lane + 64];
        float p = v0.x*k0.x + v0.y*k0.y + v0.z*k0.z + v0.w*k0.w;
        p      += v1.x*k1.x + v1.y*k1.y + v1.z*k1.z + v1.w*k1.w;
        p      += v2.x*k2.x + v2.y*k2.y + v2.z*k2.z + v2.w*k2.w;
        p = warp_sum(p);
        float sc = (p + dq) * scale;
        float wt = __expf(sc);
        if (lane == 0) sm->scores[0] = sc;
        dsum = wt;
        a0.x = wt*v0.x; a0.y = wt*v0.y; a0.z = wt*v0.z; a0.w = wt*v0.w;
        a1.x = wt*v1.x; a1.y = wt*v1.y; a1.z = wt*v1.z; a1.w = wt*v1.w;
        a2.x = wt*v2.x; a2.y = wt*v2.y; a2.z = wt*v2.z; a2.w = wt*v2.w;
    }

    for (int i = 0; i < nloc; ++i) {
        CP_WAIT(ND - 1);                    // oldest group (local row i) complete
        const int s = sm->act[w + i * NW];
        const float4* r = (const float4*)sm->stage[w][i & (ND - 1)];
        float4 v0 = r[lane], v1 = r[lane + 32], v2 = r[lane + 64];

        float p = v0.x*k0.x + v0.y*k0.y + v0.z*k0.z + v0.w*k0.w;
        p      += v1.x*k1.x + v1.y*k1.y + v1.z*k1.z + v1.w*k1.w;
        p      += v2.x*k2.x + v2.y*k2.y + v2.z*k2.z + v2.w*k2.w;
        p = warp_sum(p);

        issue_row(i + ND);                  // refill the slot just consumed

        float sc = (p + dq) * scale;
        float wt = __expf(sc);
        if (lane == 0) sm->scores[s + 1] = sc;
        dsum += wt;
        a0.x = fmaf(wt, v0.x, a0.x); a0.y = fmaf(wt, v0.y, a0.y);
        a0.z = fmaf(wt, v0.z, a0.z); a0.w = fmaf(wt, v0.w, a0.w);
        a1.x = fmaf(wt, v1.x, a1.x); a1.y = fmaf(wt, v1.y, a1.y);
        a1.z = fmaf(wt, v1.z, a1.z); a1.w = fmaf(wt, v1.w, a1.w);
        a2.x = fmaf(wt, v2.x, a2.x); a2.y = fmaf(wt, v2.y, a2.y);
        a2.z = fmaf(wt, v2.z, a2.z); a2.w = fmaf(wt, v2.w, a2.w);
    }
    CP_WAIT(0);                             // drain (tail groups are empty commits)

    if (lane == 0) sm->wd[w] = dsum;
    {
        // reuse this warp's own stage slot 0 as its accumulator dump
        float4* arow = (float4*)sm->stage[w][0];
        arow[lane] = a0; arow[lane + 32] = a1; arow[lane + 64] = a2;
    }
    __syncthreads();

    // ---------------- merge (barrier-free): every warp computes gd itself -------
    float gd_l = (lane < NW) ? sm->wd[lane] : 0.f;
    gd_l = warp_sum(gd_l);                  // warp-uniform total denominator
    const float ginv = 1.f / gd_l;

    // attn_weight output + ctx reduction (independent; STG overlaps LDS)
    {
        float* out_attn = out + BB + (size_t)b * SP1;
        for (int s = tid; s < SP1; s += NT)
            out_attn[s] = __expf(sm->scores[s]) * ginv;
    }
    if (tid < EE) {
        float c = 0.f;
        #pragma unroll
        for (int ww = 0; ww < NW; ++ww)
            c += sm->stage[ww][0][tid];
        sm->ctx[tid] = c * ginv;
    }
    __syncthreads();

    // ---------------- doc_repr = ctx @ W_v + b_v ; logits ------------------------
    {
        const int e0 = w * (EE / NW);                // 24-wide slabs
        float p = 0.f;
        #pragma unroll
        for (int j = 0; j < EE / NW; ++j)
            p = fmaf(sm->ctx[e0 + j], W_v[(e0 + j) * HH + lane], p);
        sm->doc[w][lane] = p;
    }
    __syncthreads();
    if (w == 0) {
        float dv = b_v[lane];
        #pragma unroll
        for (int g = 0; g < NW; ++g) dv += sm->doc[g][lane];
        float lg = fmaf(dv, W_c[lane], sm->q[lane] * W_c[HH + lane]);
        lg = warp_sum(lg);
        if (lane == 0) out[b] = lg + b_c[0];
    }
    __syncthreads();    // protect smem before next batch reuses it

    } // persistent batch loop
}

extern "C" void kernel_launch(void* const* d_in, const int* in_sizes, int n_in,
                              void* d_out, int out_size) {
    (void)in_sizes; (void)n_in; (void)out_size;
    const int smem_bytes = (int)sizeof(Smem);
    cudaFuncSetAttribute(sent_attn_kernel,
                         cudaFuncAttributeMaxDynamicSharedMemorySize, smem_bytes);
    sent_attn_kernel<<<GRID, NT, smem_bytes>>>(
        (const float*)d_in[0],   // embeddings
        (const int*  )d_in[1],   // masks
        (const float*)d_in[2],   // features
        (const float*)d_in[3],   // W_map
        (const float*)d_in[4],   // b_map
        (const float*)d_in[5],   // trainable
        (const float*)d_in[6],   // W_k
        (const float*)d_in[7],   // b_k
        (const float*)d_in[8],   // W_v
        (const float*)d_in[9],   // b_v
        (const float*)d_in[10],  // W_c
        (const float*)d_in[11],  // b_c
        (float*)d_out);
}